// round 4
// baseline (speedup 1.0000x reference)
#include <cuda_runtime.h>
#include <cuda_bf16.h>

// Problem dims (fixed by the dataset): N=50000 nodes, E=800000 edges,
// in_dim=128, out_dim=64. Small headroom on N.
#define MAX_N   50176
#define IN_DIM  128
#define OUT_DIM 64
#define NEG_SLOPE 0.2f

// Scratch (allocation-free: __device__ globals).
__device__ float4 g_h4[MAX_N * (OUT_DIM / 4)];    // h  [N,64]
__device__ float4 g_acc4[MAX_N * (OUT_DIM / 4)];  // acc[N,64] (numerator)
__device__ float  g_hs[MAX_N];                    // h @ a_src
__device__ float  g_hd[MAX_N];                    // h @ a_dst
__device__ float  g_s[MAX_N];                     // segment sum of exp

// ---------------------------------------------------------------------------
// K0: zero s and acc
// ---------------------------------------------------------------------------
__global__ void k_init(int N) {
    int idx = blockIdx.x * blockDim.x + threadIdx.x;
    float* acc = (float*)g_acc4;
    if (idx < N) g_s[idx] = 0.0f;
    if (idx < N * OUT_DIM) acc[idx] = 0.0f;
}

// ---------------------------------------------------------------------------
// K1: h = X @ W  (warp per row), fused hs = h@a_src, hd = h@a_dst
// ---------------------------------------------------------------------------
__global__ __launch_bounds__(256) void k_gemm(const float* __restrict__ inp,
                                              const float* __restrict__ Wg,
                                              const float* __restrict__ ag,
                                              int N) {
    __shared__ float Wsh[IN_DIM * OUT_DIM];   // 32 KB, reordered
    __shared__ float a_s[OUT_DIM], a_d[OUT_DIM];

    for (int idx = threadIdx.x; idx < IN_DIM * OUT_DIM; idx += blockDim.x) {
        int k = idx >> 6, j = idx & 63;
        int pos = (j < 32) ? (2 * j) : (2 * (j - 32) + 1);
        Wsh[(k << 6) + pos] = Wg[idx];
    }
    if (threadIdx.x < OUT_DIM) {
        a_s[threadIdx.x] = ag[threadIdx.x];
        a_d[threadIdx.x] = ag[OUT_DIM + threadIdx.x];
    }
    __syncthreads();

    int warp = threadIdx.x >> 5;
    int lane = threadIdx.x & 31;
    int row  = blockIdx.x * 8 + warp;
    if (row >= N) return;

    const float4* inrow = (const float4*)(inp + (size_t)row * IN_DIM);
    float4 v = inrow[lane];

    const float2* wp = (const float2*)Wsh;   // wp[k*32 + t] = (W[k][t], W[k][t+32])
    float acc0 = 0.0f, acc1 = 0.0f;

#pragma unroll
    for (int q = 0; q < 32; q++) {
        float b0 = __shfl_sync(0xffffffffu, v.x, q);
        float b1 = __shfl_sync(0xffffffffu, v.y, q);
        float b2 = __shfl_sync(0xffffffffu, v.z, q);
        float b3 = __shfl_sync(0xffffffffu, v.w, q);
        int k = q << 2;
        float2 w0 = wp[(k + 0) * 32 + lane];
        float2 w1 = wp[(k + 1) * 32 + lane];
        float2 w2 = wp[(k + 2) * 32 + lane];
        float2 w3 = wp[(k + 3) * 32 + lane];
        acc0 = fmaf(b0, w0.x, acc0); acc1 = fmaf(b0, w0.y, acc1);
        acc0 = fmaf(b1, w1.x, acc0); acc1 = fmaf(b1, w1.y, acc1);
        acc0 = fmaf(b2, w2.x, acc0); acc1 = fmaf(b2, w2.y, acc1);
        acc0 = fmaf(b3, w3.x, acc0); acc1 = fmaf(b3, w3.y, acc1);
    }

    // natural layout: h[row][lane] = acc0, h[row][lane+32] = acc1
    float* gh = (float*)g_h4;
    gh[(size_t)row * OUT_DIM + lane]      = acc0;
    gh[(size_t)row * OUT_DIM + lane + 32] = acc1;

    float ps = acc0 * a_s[lane] + acc1 * a_s[lane + 32];
    float pd = acc0 * a_d[lane] + acc1 * a_d[lane + 32];
#pragma unroll
    for (int o = 16; o > 0; o >>= 1) {
        ps += __shfl_xor_sync(0xffffffffu, ps, o);
        pd += __shfl_xor_sync(0xffffffffu, pd, o);
    }
    if (lane == 0) {
        g_hs[row] = ps;
        g_hd[row] = pd;
    }
}

// ---------------------------------------------------------------------------
// K2: one warp per edge. Edge indices are int32 (JAX x64 disabled downcasts
// the reference's int64 to int32 at trace time).
//   e  = leaky_relu(hs[src] + hd[dst]);  ex = exp(e)
//   (no max-shift: scores bounded, exp safe in fp32; softmax shift-invariant)
//   s[src]      += ex                      (lane 0, scalar atomic)
//   acc[src][j] += ex * h[dst][j]          (lane l handles j = l and l+32 —
//                                           128 B apart so ptxas cannot fuse
//                                           into a vector RED, which traps)
// ---------------------------------------------------------------------------
__global__ __launch_bounds__(256) void k_edge(const int* __restrict__ edge,
                                              int E) {
    int gwarp = (blockIdx.x * blockDim.x + threadIdx.x) >> 5;
    if (gwarp >= E) return;
    int lane = threadIdx.x & 31;

    int src = edge[gwarp];        // broadcast load (all lanes same addr)
    int dst = edge[E + gwarp];

    float sc = g_hs[src] + g_hd[dst];
    sc = sc > 0.0f ? sc : NEG_SLOPE * sc;
    float ex = __expf(sc);

    if (lane == 0) atomicAdd(&g_s[src], ex);

    const float* hrow = (const float*)g_h4 + (size_t)dst * OUT_DIM;
    float v0 = hrow[lane];
    float v1 = hrow[lane + 32];
    float* arow = (float*)g_acc4 + (size_t)src * OUT_DIM;
    atomicAdd(arow + lane,      ex * v0);
    atomicAdd(arow + lane + 32, ex * v1);
}

// ---------------------------------------------------------------------------
// K3: out = elu(acc / s), with s==0 -> 0 (nodes without outgoing edges)
// ---------------------------------------------------------------------------
__global__ void k_final(float* __restrict__ out, int N) {
    int idx = blockIdx.x * blockDim.x + threadIdx.x;
    if (idx >= N * OUT_DIM) return;
    int node = idx >> 6;
    float ss = g_s[node];
    const float* acc = (const float*)g_acc4;
    float r = (ss > 0.0f) ? (acc[idx] / ss) : 0.0f;
    out[idx] = (r > 0.0f) ? r : expm1f(r);
}

// ---------------------------------------------------------------------------
extern "C" void kernel_launch(void* const* d_in, const int* in_sizes, int n_in,
                              void* d_out, int out_size) {
    const float* inp  = (const float*)d_in[0];
    const int*   edge = (const int*)d_in[1];
    const float* Wg   = (const float*)d_in[2];
    const float* ag   = (const float*)d_in[3];
    float*       out  = (float*)d_out;

    int N = in_sizes[0] / IN_DIM;
    int E = in_sizes[1] / 2;

    k_init<<<(N * OUT_DIM + 255) / 256, 256>>>(N);
    k_gemm<<<(N + 7) / 8, 256>>>(inp, Wg, ag, N);
    k_edge<<<(E + 7) / 8, 256>>>(edge, E);    // 8 warps/block, 1 edge/warp
    k_final<<<(N * OUT_DIM + 255) / 256, 256>>>(out, N);
}

// round 5
// speedup vs baseline: 1.2765x; 1.2765x over previous
#include <cuda_runtime.h>
#include <cuda_bf16.h>

// Problem dims: N=50000 nodes, E=800000 edges, in_dim=128, out_dim=64.
#define MAX_N   50176
#define MAX_E   803840
#define IN_DIM  128
#define OUT_DIM 64
#define NEG_SLOPE 0.2f

// Scratch (allocation-free: __device__ globals).
__device__ float g_h[MAX_N * OUT_DIM];   // h [N,64]
__device__ float g_hs[MAX_N];            // h @ a_src
__device__ float g_hd[MAX_N];            // h @ a_dst
__device__ int   g_deg[MAX_N];           // out-degree by src
__device__ int   g_rowptr[MAX_N];        // CSR row pointers (exclusive scan)
__device__ int   g_cursor[MAX_N];        // scatter cursors
__device__ int   g_csrdst[MAX_E];        // dst ids grouped by src
__device__ int   g_part[256];            // per-chunk sums   (nchunks <= 256)
__device__ int   g_partscan[256];        // exclusive scan of chunk sums

// ---------------------------------------------------------------------------
// K0: zero degree counters
// ---------------------------------------------------------------------------
__global__ void k_zero(int N) {
    int i = blockIdx.x * blockDim.x + threadIdx.x;
    if (i < N) g_deg[i] = 0;
}

// ---------------------------------------------------------------------------
// K1: h = X @ W  (warp per row), fused hs = h@a_src, hd = h@a_dst
// ---------------------------------------------------------------------------
__global__ __launch_bounds__(256) void k_gemm(const float* __restrict__ inp,
                                              const float* __restrict__ Wg,
                                              const float* __restrict__ ag,
                                              int N) {
    __shared__ float Wsh[IN_DIM * OUT_DIM];   // 32 KB, reordered
    __shared__ float a_s[OUT_DIM], a_d[OUT_DIM];

    for (int idx = threadIdx.x; idx < IN_DIM * OUT_DIM; idx += blockDim.x) {
        int k = idx >> 6, j = idx & 63;
        int pos = (j < 32) ? (2 * j) : (2 * (j - 32) + 1);
        Wsh[(k << 6) + pos] = Wg[idx];
    }
    if (threadIdx.x < OUT_DIM) {
        a_s[threadIdx.x] = ag[threadIdx.x];
        a_d[threadIdx.x] = ag[OUT_DIM + threadIdx.x];
    }
    __syncthreads();

    int warp = threadIdx.x >> 5;
    int lane = threadIdx.x & 31;
    int row  = blockIdx.x * 8 + warp;
    if (row >= N) return;

    const float4* inrow = (const float4*)(inp + (size_t)row * IN_DIM);
    float4 v = inrow[lane];

    const float2* wp = (const float2*)Wsh;   // wp[k*32+t] = (W[k][t], W[k][t+32])
    float acc0 = 0.0f, acc1 = 0.0f;

#pragma unroll
    for (int q = 0; q < 32; q++) {
        float b0 = __shfl_sync(0xffffffffu, v.x, q);
        float b1 = __shfl_sync(0xffffffffu, v.y, q);
        float b2 = __shfl_sync(0xffffffffu, v.z, q);
        float b3 = __shfl_sync(0xffffffffu, v.w, q);
        int k = q << 2;
        float2 w0 = wp[(k + 0) * 32 + lane];
        float2 w1 = wp[(k + 1) * 32 + lane];
        float2 w2 = wp[(k + 2) * 32 + lane];
        float2 w3 = wp[(k + 3) * 32 + lane];
        acc0 = fmaf(b0, w0.x, acc0); acc1 = fmaf(b0, w0.y, acc1);
        acc0 = fmaf(b1, w1.x, acc0); acc1 = fmaf(b1, w1.y, acc1);
        acc0 = fmaf(b2, w2.x, acc0); acc1 = fmaf(b2, w2.y, acc1);
        acc0 = fmaf(b3, w3.x, acc0); acc1 = fmaf(b3, w3.y, acc1);
    }

    g_h[(size_t)row * OUT_DIM + lane]      = acc0;
    g_h[(size_t)row * OUT_DIM + lane + 32] = acc1;

    float ps = acc0 * a_s[lane] + acc1 * a_s[lane + 32];
    float pd = acc0 * a_d[lane] + acc1 * a_d[lane + 32];
#pragma unroll
    for (int o = 16; o > 0; o >>= 1) {
        ps += __shfl_xor_sync(0xffffffffu, ps, o);
        pd += __shfl_xor_sync(0xffffffffu, pd, o);
    }
    if (lane == 0) {
        g_hs[row] = ps;
        g_hd[row] = pd;
    }
}

// ---------------------------------------------------------------------------
// K2: histogram of src
// ---------------------------------------------------------------------------
__global__ void k_hist(const int* __restrict__ edge, int E) {
    int i = blockIdx.x * blockDim.x + threadIdx.x;
    if (i < E) atomicAdd(&g_deg[edge[i]], 1);
}

// ---------------------------------------------------------------------------
// K3a: per-256-chunk sums of deg
// ---------------------------------------------------------------------------
__global__ void k_scan1(int N) {
    __shared__ int sm[256];
    int t = threadIdx.x;
    int i = blockIdx.x * 256 + t;
    sm[t] = (i < N) ? g_deg[i] : 0;
    __syncthreads();
    for (int off = 128; off > 0; off >>= 1) {
        if (t < off) sm[t] += sm[t + off];
        __syncthreads();
    }
    if (t == 0) g_part[blockIdx.x] = sm[0];
}

// ---------------------------------------------------------------------------
// K3b: exclusive scan of chunk sums (single block; nchunks <= 256)
// ---------------------------------------------------------------------------
__global__ void k_scan2(int nchunks) {
    __shared__ int sm[256];
    int t = threadIdx.x;
    int v = (t < nchunks) ? g_part[t] : 0;
    sm[t] = v;
    __syncthreads();
    for (int off = 1; off < 256; off <<= 1) {
        int u = (t >= off) ? sm[t - off] : 0;
        __syncthreads();
        sm[t] += u;
        __syncthreads();
    }
    if (t < nchunks) g_partscan[t] = sm[t] - v;   // exclusive
}

// ---------------------------------------------------------------------------
// K3c: per-chunk exclusive scan + chunk base -> rowptr, cursor
// ---------------------------------------------------------------------------
__global__ void k_scan3(int N) {
    __shared__ int sm[256];
    int t = threadIdx.x;
    int i = blockIdx.x * 256 + t;
    int v = (i < N) ? g_deg[i] : 0;
    sm[t] = v;
    __syncthreads();
    for (int off = 1; off < 256; off <<= 1) {
        int u = (t >= off) ? sm[t - off] : 0;
        __syncthreads();
        sm[t] += u;
        __syncthreads();
    }
    if (i < N) {
        int p = g_partscan[blockIdx.x] + sm[t] - v;
        g_rowptr[i] = p;
        g_cursor[i] = p;
    }
}

// ---------------------------------------------------------------------------
// K4: scatter dst into CSR buckets
// ---------------------------------------------------------------------------
__global__ void k_scatter(const int* __restrict__ edge, int E) {
    int i = blockIdx.x * blockDim.x + threadIdx.x;
    if (i < E) {
        int s = edge[i];
        int d = edge[E + i];
        int pos = atomicAdd(&g_cursor[s], 1);
        g_csrdst[pos] = d;
    }
}

// ---------------------------------------------------------------------------
// K5: fused aggregate + softmax + ELU. One warp per node; all accumulation in
// registers; every lane redundantly computes ex (broadcast loads), lane l owns
// output dims 2l, 2l+1 (float2).
// No max-shift: scores bounded, exp safe in fp32; softmax shift-invariant.
// ---------------------------------------------------------------------------
__global__ __launch_bounds__(256) void k_agg(float* __restrict__ out, int N, int E) {
    int gwarp = (blockIdx.x * blockDim.x + threadIdx.x) >> 5;
    if (gwarp >= N) return;
    int lane = threadIdx.x & 31;

    int start = g_rowptr[gwarp];
    int end   = (gwarp + 1 < N) ? g_rowptr[gwarp + 1] : E;
    float hs_n = g_hs[gwarp];

    const float2* h2 = (const float2*)g_h;
    float a0 = 0.0f, a1 = 0.0f, ssum = 0.0f;

#pragma unroll 2
    for (int i = start; i < end; i++) {
        int dst = g_csrdst[i];                 // broadcast load
        float sc = hs_n + g_hd[dst];           // broadcast load
        sc = sc > 0.0f ? sc : NEG_SLOPE * sc;
        float ex = __expf(sc);
        ssum += ex;
        float2 v = h2[(size_t)dst * 32 + lane];
        a0 = fmaf(ex, v.x, a0);
        a1 = fmaf(ex, v.y, a1);
    }

    float2 r;
    if (ssum > 0.0f) {
        float inv = 1.0f / ssum;
        r.x = a0 * inv;
        r.y = a1 * inv;
    } else {
        r.x = 0.0f; r.y = 0.0f;
    }
    r.x = r.x > 0.0f ? r.x : expm1f(r.x);
    r.y = r.y > 0.0f ? r.y : expm1f(r.y);
    ((float2*)out)[(size_t)gwarp * 32 + lane] = r;
}

// ---------------------------------------------------------------------------
extern "C" void kernel_launch(void* const* d_in, const int* in_sizes, int n_in,
                              void* d_out, int out_size) {
    const float* inp  = (const float*)d_in[0];
    const int*   edge = (const int*)d_in[1];
    const float* Wg   = (const float*)d_in[2];
    const float* ag   = (const float*)d_in[3];
    float*       out  = (float*)d_out;

    int N = in_sizes[0] / IN_DIM;
    int E = in_sizes[1] / 2;
    int nchunks = (N + 255) / 256;   // <= 256 required (N <= 65536)

    k_zero   <<<(N + 255) / 256, 256>>>(N);
    k_gemm   <<<(N + 7) / 8, 256>>>(inp, Wg, ag, N);
    k_hist   <<<(E + 255) / 256, 256>>>(edge, E);
    k_scan1  <<<nchunks, 256>>>(N);
    k_scan2  <<<1, 256>>>(nchunks);
    k_scan3  <<<nchunks, 256>>>(N);
    k_scatter<<<(E + 255) / 256, 256>>>(edge, E);
    k_agg    <<<(N + 7) / 8, 256>>>(out, N, E);
}

// round 6
// speedup vs baseline: 1.2958x; 1.0152x over previous
#include <cuda_runtime.h>
#include <cuda_bf16.h>

// Problem dims: N=50000 nodes, E=800000 edges, in_dim=128, out_dim=64.
#define MAX_N   50176
#define MAX_E   803840
#define IN_DIM  128
#define OUT_DIM 64
#define NEG_SLOPE 0.2f

// Scratch (allocation-free: __device__ globals).
__device__ float g_h[MAX_N * OUT_DIM];   // h [N,64]
__device__ float g_hs[MAX_N];            // h @ a_src
__device__ float g_hd[MAX_N];            // h @ a_dst
__device__ int   g_deg[MAX_N];           // out-degree by src
__device__ int   g_rowptr[MAX_N];        // CSR row pointers (exclusive scan)
__device__ int   g_cursor[MAX_N];        // scatter cursors
__device__ int   g_csrdst[MAX_E];        // dst ids grouped by src
__device__ int   g_part[256];            // per-chunk sums (nchunks <= 256)

// ---------------------------------------------------------------------------
// K1: h = X @ W (warp per row), fused hs/hd projections; also zeroes g_deg.
// ---------------------------------------------------------------------------
__global__ __launch_bounds__(256) void k_gemm(const float* __restrict__ inp,
                                              const float* __restrict__ Wg,
                                              const float* __restrict__ ag,
                                              int N) {
    __shared__ float Wsh[IN_DIM * OUT_DIM];   // 32 KB, reordered
    __shared__ float a_s[OUT_DIM], a_d[OUT_DIM];

    // fused: zero degree counters (grid covers N amply)
    int gt = blockIdx.x * blockDim.x + threadIdx.x;
    if (gt < N) g_deg[gt] = 0;

    for (int idx = threadIdx.x; idx < IN_DIM * OUT_DIM; idx += blockDim.x) {
        int k = idx >> 6, j = idx & 63;
        int pos = (j < 32) ? (2 * j) : (2 * (j - 32) + 1);
        Wsh[(k << 6) + pos] = Wg[idx];
    }
    if (threadIdx.x < OUT_DIM) {
        a_s[threadIdx.x] = ag[threadIdx.x];
        a_d[threadIdx.x] = ag[OUT_DIM + threadIdx.x];
    }
    __syncthreads();

    int warp = threadIdx.x >> 5;
    int lane = threadIdx.x & 31;
    int row  = blockIdx.x * 8 + warp;
    if (row >= N) return;

    const float4* inrow = (const float4*)(inp + (size_t)row * IN_DIM);
    float4 v = inrow[lane];

    const float2* wp = (const float2*)Wsh;   // wp[k*32+t] = (W[k][t], W[k][t+32])
    float acc0 = 0.0f, acc1 = 0.0f;

#pragma unroll
    for (int q = 0; q < 32; q++) {
        float b0 = __shfl_sync(0xffffffffu, v.x, q);
        float b1 = __shfl_sync(0xffffffffu, v.y, q);
        float b2 = __shfl_sync(0xffffffffu, v.z, q);
        float b3 = __shfl_sync(0xffffffffu, v.w, q);
        int k = q << 2;
        float2 w0 = wp[(k + 0) * 32 + lane];
        float2 w1 = wp[(k + 1) * 32 + lane];
        float2 w2 = wp[(k + 2) * 32 + lane];
        float2 w3 = wp[(k + 3) * 32 + lane];
        acc0 = fmaf(b0, w0.x, acc0); acc1 = fmaf(b0, w0.y, acc1);
        acc0 = fmaf(b1, w1.x, acc0); acc1 = fmaf(b1, w1.y, acc1);
        acc0 = fmaf(b2, w2.x, acc0); acc1 = fmaf(b2, w2.y, acc1);
        acc0 = fmaf(b3, w3.x, acc0); acc1 = fmaf(b3, w3.y, acc1);
    }

    g_h[(size_t)row * OUT_DIM + lane]      = acc0;
    g_h[(size_t)row * OUT_DIM + lane + 32] = acc1;

    float ps = acc0 * a_s[lane] + acc1 * a_s[lane + 32];
    float pd = acc0 * a_d[lane] + acc1 * a_d[lane + 32];
#pragma unroll
    for (int o = 16; o > 0; o >>= 1) {
        ps += __shfl_xor_sync(0xffffffffu, ps, o);
        pd += __shfl_xor_sync(0xffffffffu, pd, o);
    }
    if (lane == 0) {
        g_hs[row] = ps;
        g_hd[row] = pd;
    }
}

// ---------------------------------------------------------------------------
// K2: histogram of src (int4-vectorized)
// ---------------------------------------------------------------------------
__global__ void k_hist(const int* __restrict__ edge, int E) {
    int i4 = blockIdx.x * blockDim.x + threadIdx.x;
    int base = i4 * 4;
    if (base + 3 < E) {
        int4 e = *(const int4*)(edge + base);
        atomicAdd(&g_deg[e.x], 1);
        atomicAdd(&g_deg[e.y], 1);
        atomicAdd(&g_deg[e.z], 1);
        atomicAdd(&g_deg[e.w], 1);
    } else {
        for (int i = base; i < E; i++) atomicAdd(&g_deg[edge[i]], 1);
    }
}

// ---------------------------------------------------------------------------
// K3a: per-256-chunk sums of deg
// ---------------------------------------------------------------------------
__global__ void k_scan1(int N) {
    __shared__ int sm[256];
    int t = threadIdx.x;
    int i = blockIdx.x * 256 + t;
    sm[t] = (i < N) ? g_deg[i] : 0;
    __syncthreads();
    for (int off = 128; off > 0; off >>= 1) {
        if (t < off) sm[t] += sm[t + off];
        __syncthreads();
    }
    if (t == 0) g_part[blockIdx.x] = sm[0];
}

// ---------------------------------------------------------------------------
// K3b (fused): every block redundantly scans the chunk partials (<=256) to get
// its base, then does its per-chunk exclusive scan -> rowptr, cursor.
// ---------------------------------------------------------------------------
__global__ void k_scan3(int N, int nchunks) {
    __shared__ int sp[256];
    __shared__ int sm[256];
    int t = threadIdx.x;

    // redundant exclusive scan of chunk sums
    int pv = (t < nchunks) ? g_part[t] : 0;
    sp[t] = pv;
    __syncthreads();
    for (int off = 1; off < 256; off <<= 1) {
        int u = (t >= off) ? sp[t - off] : 0;
        __syncthreads();
        sp[t] += u;
        __syncthreads();
    }
    int chunk_base = (blockIdx.x > 0) ? sp[blockIdx.x - 1] : 0;

    // per-chunk scan
    int i = blockIdx.x * 256 + t;
    int v = (i < N) ? g_deg[i] : 0;
    sm[t] = v;
    __syncthreads();
    for (int off = 1; off < 256; off <<= 1) {
        int u = (t >= off) ? sm[t - off] : 0;
        __syncthreads();
        sm[t] += u;
        __syncthreads();
    }
    if (i < N) {
        int p = chunk_base + sm[t] - v;
        g_rowptr[i] = p;
        g_cursor[i] = p;
    }
}

// ---------------------------------------------------------------------------
// K4: scatter dst into CSR buckets
// ---------------------------------------------------------------------------
__global__ void k_scatter(const int* __restrict__ edge, int E) {
    int i = blockIdx.x * blockDim.x + threadIdx.x;
    if (i < E) {
        int s = edge[i];
        int d = edge[E + i];
        int pos = atomicAdd(&g_cursor[s], 1);
        g_csrdst[pos] = d;
    }
}

// ---------------------------------------------------------------------------
// K5: fused aggregate + softmax + ELU. One warp per node.
// 32 edges processed per outer iteration: coalesced csrdst load, parallel hd
// gather + exp (one edge per lane), then shuffle-broadcast into the FMA loop.
// Softmax denominator accumulated as per-lane partials, butterfly-reduced once.
// No max-shift: scores bounded, exp safe in fp32; softmax shift-invariant.
// ---------------------------------------------------------------------------
__global__ __launch_bounds__(256) void k_agg(float* __restrict__ out, int N, int E) {
    int gwarp = (blockIdx.x * blockDim.x + threadIdx.x) >> 5;
    if (gwarp >= N) return;
    int lane = threadIdx.x & 31;

    int start = g_rowptr[gwarp];
    int end   = (gwarp + 1 < N) ? g_rowptr[gwarp + 1] : E;
    float hs_n = g_hs[gwarp];

    const float2* h2 = (const float2*)g_h;
    float a0 = 0.0f, a1 = 0.0f, spart = 0.0f;

    for (int base = start; base < end; base += 32) {
        int i = base + lane;
        bool act = (i < end);
        int dst = act ? g_csrdst[i] : 0;          // coalesced
        float hdv = act ? g_hd[dst] : 0.0f;       // parallel gather
        float sc = hs_n + hdv;
        sc = sc > 0.0f ? sc : NEG_SLOPE * sc;
        float ex = act ? __expf(sc) : 0.0f;
        spart += ex;

        int cnt = min(32, end - base);
#pragma unroll 4
        for (int j = 0; j < cnt; j++) {
            float exj = __shfl_sync(0xffffffffu, ex, j);
            int dstj  = __shfl_sync(0xffffffffu, dst, j);
            float2 v = h2[(size_t)dstj * 32 + lane];
            a0 = fmaf(exj, v.x, a0);
            a1 = fmaf(exj, v.y, a1);
        }
    }

    // reduce softmax denominator across lanes
#pragma unroll
    for (int o = 16; o > 0; o >>= 1)
        spart += __shfl_xor_sync(0xffffffffu, spart, o);

    float2 r;
    if (spart > 0.0f) {
        float inv = 1.0f / spart;
        r.x = a0 * inv;
        r.y = a1 * inv;
    } else {
        r.x = 0.0f; r.y = 0.0f;
    }
    r.x = r.x > 0.0f ? r.x : expm1f(r.x);
    r.y = r.y > 0.0f ? r.y : expm1f(r.y);
    ((float2*)out)[(size_t)gwarp * 32 + lane] = r;
}

// ---------------------------------------------------------------------------
extern "C" void kernel_launch(void* const* d_in, const int* in_sizes, int n_in,
                              void* d_out, int out_size) {
    const float* inp  = (const float*)d_in[0];
    const int*   edge = (const int*)d_in[1];
    const float* Wg   = (const float*)d_in[2];
    const float* ag   = (const float*)d_in[3];
    float*       out  = (float*)d_out;

    int N = in_sizes[0] / IN_DIM;
    int E = in_sizes[1] / 2;
    int nchunks = (N + 255) / 256;   // <= 256 required (N <= 65536)

    k_gemm   <<<(N + 7) / 8, 256>>>(inp, Wg, ag, N);     // also zeroes g_deg
    k_hist   <<<(E / 4 + 255) / 256, 256>>>(edge, E);
    k_scan1  <<<nchunks, 256>>>(N);
    k_scan3  <<<nchunks, 256>>>(N, nchunks);
    k_scatter<<<(E + 255) / 256, 256>>>(edge, E);
    k_agg    <<<(N + 7) / 8, 256>>>(out, N, E);
}

// round 7
// speedup vs baseline: 1.3510x; 1.0426x over previous
#include <cuda_runtime.h>
#include <cuda_bf16.h>

// Problem dims: N=50000 nodes, E=800000 edges, in_dim=128, out_dim=64.
#define MAX_N   50176
#define MAX_E   803840
#define IN_DIM  128
#define OUT_DIM 64
#define NEG_SLOPE 0.2f

// Scratch (allocation-free: __device__ globals; zero-initialized at load).
__device__ float g_h[MAX_N * OUT_DIM];   // h [N,64]
__device__ float g_hs[MAX_N];            // h @ a_src
__device__ float g_hd[MAX_N];            // h @ a_dst
__device__ int   g_deg[MAX_N];           // out-degree by src (zeroed by k_agg of prior call)
__device__ int   g_rowptr[MAX_N];        // CSR row pointers (exclusive scan)
__device__ int   g_cursor[MAX_N];        // scatter cursors
__device__ int   g_csrdst[MAX_E];        // dst ids grouped by src
// decoupled-lookback scan state (flags zeroed by k_scatter of prior call)
__device__ volatile int g_blockagg[256];
__device__ volatile int g_blockpre[256];
__device__ volatile int g_flag[256];     // 0=none, 1=aggregate, 2=prefix

// ---------------------------------------------------------------------------
// K1: h = X @ W (32 rows/block, 4 rows/warp) + fused hs/hd projections
//     + fused src histogram (grid-stride REDs issued up-front, drain during
//       the GEMM compute).
// ---------------------------------------------------------------------------
__global__ __launch_bounds__(256) void k_gemm(const float* __restrict__ inp,
                                              const float* __restrict__ Wg,
                                              const float* __restrict__ ag,
                                              const int* __restrict__ edge,
                                              int N, int E) {
    __shared__ float Wsh[IN_DIM * OUT_DIM];   // 32 KB, reordered
    __shared__ float a_s[OUT_DIM], a_d[OUT_DIM];

    // fused histogram of edge src (g_deg pre-zeroed)
    int gt = blockIdx.x * blockDim.x + threadIdx.x;
    int nth = gridDim.x * blockDim.x;
    for (int i = gt; i < E; i += nth) atomicAdd(&g_deg[edge[i]], 1);

    for (int idx = threadIdx.x; idx < IN_DIM * OUT_DIM; idx += blockDim.x) {
        int k = idx >> 6, j = idx & 63;
        int pos = (j < 32) ? (2 * j) : (2 * (j - 32) + 1);
        Wsh[(k << 6) + pos] = Wg[idx];
    }
    if (threadIdx.x < OUT_DIM) {
        a_s[threadIdx.x] = ag[threadIdx.x];
        a_d[threadIdx.x] = ag[OUT_DIM + threadIdx.x];
    }
    __syncthreads();

    int warp = threadIdx.x >> 5;
    int lane = threadIdx.x & 31;
    const float2* wp = (const float2*)Wsh;   // wp[k*32+t] = (W[k][t], W[k][t+32])

#pragma unroll 1
    for (int r = 0; r < 4; r++) {
        int row = blockIdx.x * 32 + warp * 4 + r;
        if (row >= N) break;

        const float4* inrow = (const float4*)(inp + (size_t)row * IN_DIM);
        float4 v = inrow[lane];
        float acc0 = 0.0f, acc1 = 0.0f;

#pragma unroll
        for (int q = 0; q < 32; q++) {
            float b0 = __shfl_sync(0xffffffffu, v.x, q);
            float b1 = __shfl_sync(0xffffffffu, v.y, q);
            float b2 = __shfl_sync(0xffffffffu, v.z, q);
            float b3 = __shfl_sync(0xffffffffu, v.w, q);
            int k = q << 2;
            float2 w0 = wp[(k + 0) * 32 + lane];
            float2 w1 = wp[(k + 1) * 32 + lane];
            float2 w2 = wp[(k + 2) * 32 + lane];
            float2 w3 = wp[(k + 3) * 32 + lane];
            acc0 = fmaf(b0, w0.x, acc0); acc1 = fmaf(b0, w0.y, acc1);
            acc0 = fmaf(b1, w1.x, acc0); acc1 = fmaf(b1, w1.y, acc1);
            acc0 = fmaf(b2, w2.x, acc0); acc1 = fmaf(b2, w2.y, acc1);
            acc0 = fmaf(b3, w3.x, acc0); acc1 = fmaf(b3, w3.y, acc1);
        }

        g_h[(size_t)row * OUT_DIM + lane]      = acc0;
        g_h[(size_t)row * OUT_DIM + lane + 32] = acc1;

        float ps = acc0 * a_s[lane] + acc1 * a_s[lane + 32];
        float pd = acc0 * a_d[lane] + acc1 * a_d[lane + 32];
#pragma unroll
        for (int o = 16; o > 0; o >>= 1) {
            ps += __shfl_xor_sync(0xffffffffu, ps, o);
            pd += __shfl_xor_sync(0xffffffffu, pd, o);
        }
        if (lane == 0) {
            g_hs[row] = ps;
            g_hd[row] = pd;
        }
    }
}

// ---------------------------------------------------------------------------
// K2: single-pass exclusive scan of g_deg -> rowptr/cursor (decoupled
// lookback; 196 blocks, all resident on 148 SMs -> lookback terminates).
// ---------------------------------------------------------------------------
__global__ __launch_bounds__(256) void k_scan(int N) {
    __shared__ int sm[256];
    __shared__ int s_base;
    int t = threadIdx.x, b = blockIdx.x;
    int i = b * 256 + t;
    int v = (i < N) ? g_deg[i] : 0;

    // inclusive scan in smem (Hillis-Steele)
    sm[t] = v;
    __syncthreads();
    for (int off = 1; off < 256; off <<= 1) {
        int u = (t >= off) ? sm[t - off] : 0;
        __syncthreads();
        sm[t] += u;
        __syncthreads();
    }
    int total = sm[255];

    if (t == 0) {
        if (b == 0) {
            g_blockpre[0] = total;
            __threadfence();
            g_flag[0] = 2;
            s_base = 0;
        } else {
            g_blockagg[b] = total;
            __threadfence();
            g_flag[b] = 1;
            int base = 0;
            for (int j = b - 1; j >= 0; j--) {
                int f;
                while ((f = g_flag[j]) == 0) { }
                if (f == 2) { base += g_blockpre[j]; break; }
                base += g_blockagg[j];
            }
            g_blockpre[b] = base + total;
            __threadfence();
            g_flag[b] = 2;
            s_base = base;
        }
    }
    __syncthreads();

    if (i < N) {
        int p = s_base + sm[t] - v;   // exclusive
        g_rowptr[i] = p;
        g_cursor[i] = p;
    }
}

// ---------------------------------------------------------------------------
// K3: scatter dst into CSR buckets; block 0 also resets scan flags for the
// next call (safe: k_scan has fully completed).
// ---------------------------------------------------------------------------
__global__ void k_scatter(const int* __restrict__ edge, int E) {
    if (blockIdx.x == 0) g_flag[threadIdx.x] = 0;
    int i = blockIdx.x * blockDim.x + threadIdx.x;
    if (i < E) {
        int s = edge[i];
        int d = edge[E + i];
        int pos = atomicAdd(&g_cursor[s], 1);
        g_csrdst[pos] = d;
    }
}

// ---------------------------------------------------------------------------
// K4: fused aggregate + softmax + ELU. One warp per node; 32 edges per outer
// iteration (coalesced csrdst load, one exp per lane, shuffle-broadcast into
// the FMA gather loop). Also resets g_deg for the next call.
// No max-shift: scores bounded, exp safe in fp32; softmax shift-invariant.
// ---------------------------------------------------------------------------
__global__ __launch_bounds__(256) void k_agg(float* __restrict__ out, int N, int E) {
    int gwarp = (blockIdx.x * blockDim.x + threadIdx.x) >> 5;
    if (gwarp >= N) return;
    int lane = threadIdx.x & 31;

    if (lane == 0) g_deg[gwarp] = 0;   // reset for next call

    int start = g_rowptr[gwarp];
    int end   = (gwarp + 1 < N) ? g_rowptr[gwarp + 1] : E;
    float hs_n = g_hs[gwarp];

    const float2* h2 = (const float2*)g_h;
    float a0 = 0.0f, a1 = 0.0f, spart = 0.0f;

    for (int base = start; base < end; base += 32) {
        int i = base + lane;
        bool act = (i < end);
        int dst = act ? g_csrdst[i] : 0;          // coalesced
        float hdv = act ? g_hd[dst] : 0.0f;       // parallel gather
        float sc = hs_n + hdv;
        sc = sc > 0.0f ? sc : NEG_SLOPE * sc;
        float ex = act ? __expf(sc) : 0.0f;
        spart += ex;

        int cnt = min(32, end - base);
#pragma unroll 4
        for (int j = 0; j < cnt; j++) {
            float exj = __shfl_sync(0xffffffffu, ex, j);
            int dstj  = __shfl_sync(0xffffffffu, dst, j);
            float2 v = h2[(size_t)dstj * 32 + lane];
            a0 = fmaf(exj, v.x, a0);
            a1 = fmaf(exj, v.y, a1);
        }
    }

#pragma unroll
    for (int o = 16; o > 0; o >>= 1)
        spart += __shfl_xor_sync(0xffffffffu, spart, o);

    float2 r;
    if (spart > 0.0f) {
        float inv = 1.0f / spart;
        r.x = a0 * inv;
        r.y = a1 * inv;
    } else {
        r.x = 0.0f; r.y = 0.0f;
    }
    r.x = r.x > 0.0f ? r.x : expm1f(r.x);
    r.y = r.y > 0.0f ? r.y : expm1f(r.y);
    ((float2*)out)[(size_t)gwarp * 32 + lane] = r;
}

// ---------------------------------------------------------------------------
extern "C" void kernel_launch(void* const* d_in, const int* in_sizes, int n_in,
                              void* d_out, int out_size) {
    const float* inp  = (const float*)d_in[0];
    const int*   edge = (const int*)d_in[1];
    const float* Wg   = (const float*)d_in[2];
    const float* ag   = (const float*)d_in[3];
    float*       out  = (float*)d_out;

    int N = in_sizes[0] / IN_DIM;
    int E = in_sizes[1] / 2;
    int nchunks = (N + 255) / 256;   // <= 256 required (N <= 65536)

    k_gemm   <<<(N + 31) / 32, 256>>>(inp, Wg, ag, edge, N, E);  // + histogram
    k_scan   <<<nchunks, 256>>>(N);                               // single-pass
    k_scatter<<<(E + 255) / 256, 256>>>(edge, E);                 // + flag reset
    k_agg    <<<(N + 7) / 8, 256>>>(out, N, E);                   // + deg reset
}

// round 8
// speedup vs baseline: 2.0465x; 1.5147x over previous
#include <cuda_runtime.h>
#include <cuda_bf16.h>

// Problem dims: N=50000 nodes, E=800000 edges, in_dim=128, out_dim=64.
#define MAX_N   50176
#define MAX_E   803840
#define IN_DIM  128
#define OUT_DIM 64
#define NEG_SLOPE 0.2f

// Scratch (allocation-free: __device__ globals; zero-initialized at load).
__device__ float g_h[MAX_N * OUT_DIM];   // h [N,64]
__device__ float g_hs[MAX_N];            // h @ a_src
__device__ float g_hd[MAX_N];            // h @ a_dst
__device__ int   g_deg[MAX_N];           // out-degree by src (zeroed by k_agg of prior call)
__device__ int   g_rowptr[MAX_N];        // CSR row pointers (exclusive scan)
__device__ int   g_cursor[MAX_N];        // scatter cursors
__device__ int   g_csrdst[MAX_E];        // dst ids grouped by src
// decoupled-lookback scan state (flags zeroed by k_scatter of prior call)
__device__ volatile int g_blockagg[256];
__device__ volatile int g_blockpre[256];
__device__ volatile int g_flag[256];     // 0=none, 1=aggregate, 2=prefix

// ---------------------------------------------------------------------------
// K1: h = X @ W, tiled: block = 128 rows x 64 cols, thread = 8 rows x 4 cols.
//     Fused: src histogram (drains behind compute) and hs/hd projections.
// ---------------------------------------------------------------------------
#define AS_STRIDE 132
__global__ __launch_bounds__(256) void k_gemm(const float* __restrict__ inp,
                                              const float* __restrict__ Wg,
                                              const float* __restrict__ ag,
                                              const int* __restrict__ edge,
                                              int N, int E) {
    __shared__ float Ws[IN_DIM * OUT_DIM];      // W[k][col], 32 KB
    __shared__ float As[16 * AS_STRIDE];        // A-chunk transposed [k][row]
    __shared__ float a_s[OUT_DIM], a_d[OUT_DIM];

    int tid = threadIdx.x;
    // fused histogram of edge src (g_deg pre-zeroed)
    {
        int gt = blockIdx.x * 256 + tid;
        int nth = gridDim.x * 256;
        for (int i = gt; i < E; i += nth) atomicAdd(&g_deg[edge[i]], 1);
    }

    // W is [k][col] row-major already -> plain copy (float4)
    {
        const float4* src4 = (const float4*)Wg;
        float4* dst4 = (float4*)Ws;
        for (int i = tid; i < IN_DIM * OUT_DIM / 4; i += 256) dst4[i] = src4[i];
    }
    if (tid < OUT_DIM) {
        a_s[tid] = ag[tid];
        a_d[tid] = ag[OUT_DIM + tid];
    }

    int c = tid & 15;          // col group: cols c*4 .. c*4+3
    int r = tid >> 4;          // row group: rows r*8 .. r*8+7
    int row0 = blockIdx.x * 128;

    float acc[8][4];
#pragma unroll
    for (int i = 0; i < 8; i++)
#pragma unroll
        for (int j = 0; j < 4; j++) acc[i][j] = 0.0f;

    // load indices for A staging: thread loads 2 float4s per chunk
    int lrow0 = tid >> 2;            // 0..63
    int lkp   = tid & 3;             // 0..3 (float4 within the 16-wide chunk)

#pragma unroll 1
    for (int kc = 0; kc < 8; kc++) {
        __syncthreads();
        // stage A[128][16] chunk, transposed to As[k][row]
#pragma unroll
        for (int half = 0; half < 2; half++) {
            int row = lrow0 + half * 64;
            int grow = row0 + row;
            float4 av = (grow < N)
                ? *(const float4*)(inp + (size_t)grow * IN_DIM + kc * 16 + lkp * 4)
                : make_float4(0.f, 0.f, 0.f, 0.f);
            int kb = lkp * 4;
            As[(kb + 0) * AS_STRIDE + row] = av.x;
            As[(kb + 1) * AS_STRIDE + row] = av.y;
            As[(kb + 2) * AS_STRIDE + row] = av.z;
            As[(kb + 3) * AS_STRIDE + row] = av.w;
        }
        __syncthreads();

#pragma unroll
        for (int kk = 0; kk < 16; kk++) {
            int kg = kc * 16 + kk;
            float4 w = *(const float4*)(Ws + kg * OUT_DIM + c * 4);
            float4 aLo = *(const float4*)(As + kk * AS_STRIDE + r * 8);
            float4 aHi = *(const float4*)(As + kk * AS_STRIDE + r * 8 + 4);
            float a[8] = {aLo.x, aLo.y, aLo.z, aLo.w, aHi.x, aHi.y, aHi.z, aHi.w};
#pragma unroll
            for (int i = 0; i < 8; i++) {
                acc[i][0] = fmaf(a[i], w.x, acc[i][0]);
                acc[i][1] = fmaf(a[i], w.y, acc[i][1]);
                acc[i][2] = fmaf(a[i], w.z, acc[i][2]);
                acc[i][3] = fmaf(a[i], w.w, acc[i][3]);
            }
        }
    }

    // write h (float4 per row), guarded
#pragma unroll
    for (int i = 0; i < 8; i++) {
        int grow = row0 + r * 8 + i;
        if (grow < N) {
            float4 v = make_float4(acc[i][0], acc[i][1], acc[i][2], acc[i][3]);
            *(float4*)(g_h + (size_t)grow * OUT_DIM + c * 4) = v;
        }
    }

    // hs/hd: per-row dot with a_s/a_d; partial over this thread's 4 cols,
    // reduced across the 16 col-groups (lanes (r&1)*16 .. +15 of the warp).
    float4 asv = *(const float4*)(a_s + c * 4);
    float4 adv = *(const float4*)(a_d + c * 4);
#pragma unroll
    for (int i = 0; i < 8; i++) {
        float ps = acc[i][0] * asv.x + acc[i][1] * asv.y +
                   acc[i][2] * asv.z + acc[i][3] * asv.w;
        float pd = acc[i][0] * adv.x + acc[i][1] * adv.y +
                   acc[i][2] * adv.z + acc[i][3] * adv.w;
#pragma unroll
        for (int o = 8; o > 0; o >>= 1) {
            ps += __shfl_xor_sync(0xffffffffu, ps, o);
            pd += __shfl_xor_sync(0xffffffffu, pd, o);
        }
        int grow = row0 + r * 8 + i;
        if (c == 0 && grow < N) {
            g_hs[grow] = ps;
            g_hd[grow] = pd;
        }
    }
}

// ---------------------------------------------------------------------------
// K2: single-pass exclusive scan of g_deg -> rowptr/cursor (decoupled
// lookback; 196 blocks, all resident on 148 SMs -> lookback terminates).
// ---------------------------------------------------------------------------
__global__ __launch_bounds__(256) void k_scan(int N) {
    __shared__ int sm[256];
    __shared__ int s_base;
    int t = threadIdx.x, b = blockIdx.x;
    int i = b * 256 + t;
    int v = (i < N) ? g_deg[i] : 0;

    sm[t] = v;
    __syncthreads();
    for (int off = 1; off < 256; off <<= 1) {
        int u = (t >= off) ? sm[t - off] : 0;
        __syncthreads();
        sm[t] += u;
        __syncthreads();
    }
    int total = sm[255];

    if (t == 0) {
        if (b == 0) {
            g_blockpre[0] = total;
            __threadfence();
            g_flag[0] = 2;
            s_base = 0;
        } else {
            g_blockagg[b] = total;
            __threadfence();
            g_flag[b] = 1;
            int base = 0;
            for (int j = b - 1; j >= 0; j--) {
                int f;
                while ((f = g_flag[j]) == 0) { }
                if (f == 2) { base += g_blockpre[j]; break; }
                base += g_blockagg[j];
            }
            g_blockpre[b] = base + total;
            __threadfence();
            g_flag[b] = 2;
            s_base = base;
        }
    }
    __syncthreads();

    if (i < N) {
        int p = s_base + sm[t] - v;   // exclusive
        g_rowptr[i] = p;
        g_cursor[i] = p;
    }
}

// ---------------------------------------------------------------------------
// K3: scatter dst into CSR buckets; block 0 also resets scan flags.
// ---------------------------------------------------------------------------
__global__ void k_scatter(const int* __restrict__ edge, int E) {
    if (blockIdx.x == 0) g_flag[threadIdx.x] = 0;
    int i = blockIdx.x * blockDim.x + threadIdx.x;
    if (i < E) {
        int s = edge[i];
        int d = edge[E + i];
        int pos = atomicAdd(&g_cursor[s], 1);
        g_csrdst[pos] = d;
    }
}

// ---------------------------------------------------------------------------
// K4: fused aggregate + softmax + ELU. One warp per node; 32 edges per outer
// iteration. Also resets g_deg for the next call.
// No max-shift: scores bounded, exp safe in fp32; softmax shift-invariant.
// ---------------------------------------------------------------------------
__global__ __launch_bounds__(256) void k_agg(float* __restrict__ out, int N, int E) {
    int gwarp = (blockIdx.x * blockDim.x + threadIdx.x) >> 5;
    if (gwarp >= N) return;
    int lane = threadIdx.x & 31;

    if (lane == 0) g_deg[gwarp] = 0;   // reset for next call

    int start = g_rowptr[gwarp];
    int end   = (gwarp + 1 < N) ? g_rowptr[gwarp + 1] : E;
    float hs_n = g_hs[gwarp];

    const float2* h2 = (const float2*)g_h;
    float a0 = 0.0f, a1 = 0.0f, spart = 0.0f;

    for (int base = start; base < end; base += 32) {
        int i = base + lane;
        bool act = (i < end);
        int dst = act ? g_csrdst[i] : 0;          // coalesced
        float hdv = act ? g_hd[dst] : 0.0f;       // parallel gather
        float sc = hs_n + hdv;
        sc = sc > 0.0f ? sc : NEG_SLOPE * sc;
        float ex = act ? __expf(sc) : 0.0f;
        spart += ex;

        int cnt = min(32, end - base);
#pragma unroll 4
        for (int j = 0; j < cnt; j++) {
            float exj = __shfl_sync(0xffffffffu, ex, j);
            int dstj  = __shfl_sync(0xffffffffu, dst, j);
            float2 v = h2[(size_t)dstj * 32 + lane];
            a0 = fmaf(exj, v.x, a0);
            a1 = fmaf(exj, v.y, a1);
        }
    }

#pragma unroll
    for (int o = 16; o > 0; o >>= 1)
        spart += __shfl_xor_sync(0xffffffffu, spart, o);

    float2 r;
    if (spart > 0.0f) {
        float inv = 1.0f / spart;
        r.x = a0 * inv;
        r.y = a1 * inv;
    } else {
        r.x = 0.0f; r.y = 0.0f;
    }
    r.x = r.x > 0.0f ? r.x : expm1f(r.x);
    r.y = r.y > 0.0f ? r.y : expm1f(r.y);
    ((float2*)out)[(size_t)gwarp * 32 + lane] = r;
}

// ---------------------------------------------------------------------------
extern "C" void kernel_launch(void* const* d_in, const int* in_sizes, int n_in,
                              void* d_out, int out_size) {
    const float* inp  = (const float*)d_in[0];
    const int*   edge = (const int*)d_in[1];
    const float* Wg   = (const float*)d_in[2];
    const float* ag   = (const float*)d_in[3];
    float*       out  = (float*)d_out;

    int N = in_sizes[0] / IN_DIM;
    int E = in_sizes[1] / 2;
    int nchunks = (N + 255) / 256;   // <= 256 required (N <= 65536)

    k_gemm   <<<(N + 127) / 128, 256>>>(inp, Wg, ag, edge, N, E);  // + histogram
    k_scan   <<<nchunks, 256>>>(N);                                 // single-pass
    k_scatter<<<(E + 255) / 256, 256>>>(edge, E);                   // + flag reset
    k_agg    <<<(N + 7) / 8, 256>>>(out, N, E);                     // + deg reset
}

// round 10
// speedup vs baseline: 2.2332x; 1.0912x over previous
#include <cuda_runtime.h>
#include <cuda_fp16.h>

// Problem dims: N=50000 nodes, E=800000 edges, in_dim=128, out_dim=64.
#define MAX_N   50176
#define MAX_E   803840
#define IN_DIM  128
#define OUT_DIM 64
#define NEG_SLOPE 0.2f

// Scratch (allocation-free: __device__ globals; zero-initialized at load).
__device__ __half2 g_hh2[MAX_N * (OUT_DIM / 2)];  // h [N,64] as half2
__device__ float g_hs[MAX_N];            // h @ a_src (fp32)
__device__ float g_hd[MAX_N];            // h @ a_dst (fp32)
__device__ int   g_deg[MAX_N];           // out-degree by src (zeroed by k_agg of prior call)
__device__ int   g_rowptr[MAX_N];        // CSR row pointers (exclusive scan)
__device__ int   g_cursor[MAX_N];        // scatter cursors
__device__ int   g_csrdst[MAX_E];        // dst ids grouped by src
// decoupled-lookback scan state (flags zeroed by k_scatter of prior call)
__device__ volatile int g_blockagg[256];
__device__ volatile int g_blockpre[256];
__device__ volatile int g_flag[256];     // 0=none, 1=aggregate, 2=prefix

// ---------------------------------------------------------------------------
// K1: h = X @ W, tiled: block = 128 rows x 64 cols, thread = 8 rows x 4 cols.
//     h stored as half2 (only consumer is the k_agg gather).
//     Fused: src histogram (drains behind compute) and hs/hd projections (fp32).
// ---------------------------------------------------------------------------
#define AS_STRIDE 132
__global__ __launch_bounds__(256) void k_gemm(const float* __restrict__ inp,
                                              const float* __restrict__ Wg,
                                              const float* __restrict__ ag,
                                              const int* __restrict__ edge,
                                              int N, int E) {
    __shared__ float Ws[IN_DIM * OUT_DIM];      // W[k][col], 32 KB
    __shared__ float As[16 * AS_STRIDE];        // A-chunk transposed [k][row]
    __shared__ float a_s[OUT_DIM], a_d[OUT_DIM];

    int tid = threadIdx.x;
    // fused histogram of edge src (g_deg pre-zeroed)
    {
        int gt = blockIdx.x * 256 + tid;
        int nth = gridDim.x * 256;
        for (int i = gt; i < E; i += nth) atomicAdd(&g_deg[edge[i]], 1);
    }

    // W is [k][col] row-major already -> plain copy (float4)
    {
        const float4* src4 = (const float4*)Wg;
        float4* dst4 = (float4*)Ws;
        for (int i = tid; i < IN_DIM * OUT_DIM / 4; i += 256) dst4[i] = src4[i];
    }
    if (tid < OUT_DIM) {
        a_s[tid] = ag[tid];
        a_d[tid] = ag[OUT_DIM + tid];
    }

    int c = tid & 15;          // col group: cols c*4 .. c*4+3
    int r = tid >> 4;          // row group: rows r*8 .. r*8+7
    int row0 = blockIdx.x * 128;

    float acc[8][4];
#pragma unroll
    for (int i = 0; i < 8; i++)
#pragma unroll
        for (int j = 0; j < 4; j++) acc[i][j] = 0.0f;

    int lrow0 = tid >> 2;            // 0..63
    int lkp   = tid & 3;             // 0..3

#pragma unroll 1
    for (int kc = 0; kc < 8; kc++) {
        __syncthreads();
#pragma unroll
        for (int half = 0; half < 2; half++) {
            int row = lrow0 + half * 64;
            int grow = row0 + row;
            float4 av = (grow < N)
                ? *(const float4*)(inp + (size_t)grow * IN_DIM + kc * 16 + lkp * 4)
                : make_float4(0.f, 0.f, 0.f, 0.f);
            int kb = lkp * 4;
            As[(kb + 0) * AS_STRIDE + row] = av.x;
            As[(kb + 1) * AS_STRIDE + row] = av.y;
            As[(kb + 2) * AS_STRIDE + row] = av.z;
            As[(kb + 3) * AS_STRIDE + row] = av.w;
        }
        __syncthreads();

#pragma unroll
        for (int kk = 0; kk < 16; kk++) {
            int kg = kc * 16 + kk;
            float4 w = *(const float4*)(Ws + kg * OUT_DIM + c * 4);
            float4 aLo = *(const float4*)(As + kk * AS_STRIDE + r * 8);
            float4 aHi = *(const float4*)(As + kk * AS_STRIDE + r * 8 + 4);
            float a[8] = {aLo.x, aLo.y, aLo.z, aLo.w, aHi.x, aHi.y, aHi.z, aHi.w};
#pragma unroll
            for (int i = 0; i < 8; i++) {
                acc[i][0] = fmaf(a[i], w.x, acc[i][0]);
                acc[i][1] = fmaf(a[i], w.y, acc[i][1]);
                acc[i][2] = fmaf(a[i], w.z, acc[i][2]);
                acc[i][3] = fmaf(a[i], w.w, acc[i][3]);
            }
        }
    }

    // write h as half2 pairs (cols c*4..c*4+3 -> half2 indices 2c, 2c+1)
#pragma unroll
    for (int i = 0; i < 8; i++) {
        int grow = row0 + r * 8 + i;
        if (grow < N) {
            __half2* dst = g_hh2 + (size_t)grow * 32 + c * 2;
            dst[0] = __floats2half2_rn(acc[i][0], acc[i][1]);
            dst[1] = __floats2half2_rn(acc[i][2], acc[i][3]);
        }
    }

    // hs/hd: per-row dot with a_s/a_d; reduced across the 16 col-groups
    float4 asv = *(const float4*)(a_s + c * 4);
    float4 adv = *(const float4*)(a_d + c * 4);
#pragma unroll
    for (int i = 0; i < 8; i++) {
        float ps = acc[i][0] * asv.x + acc[i][1] * asv.y +
                   acc[i][2] * asv.z + acc[i][3] * asv.w;
        float pd = acc[i][0] * adv.x + acc[i][1] * adv.y +
                   acc[i][2] * adv.z + acc[i][3] * adv.w;
#pragma unroll
        for (int o = 8; o > 0; o >>= 1) {
            ps += __shfl_xor_sync(0xffffffffu, ps, o);
            pd += __shfl_xor_sync(0xffffffffu, pd, o);
        }
        int grow = row0 + r * 8 + i;
        if (c == 0 && grow < N) {
            g_hs[grow] = ps;
            g_hd[grow] = pd;
        }
    }
}

// ---------------------------------------------------------------------------
// K2: single-pass exclusive scan of g_deg -> rowptr/cursor (decoupled
// lookback; shuffle-based block scan, 2 barriers).
// ---------------------------------------------------------------------------
__global__ __launch_bounds__(256) void k_scan(int N) {
    __shared__ int wsum[8];
    __shared__ int s_base;
    int t = threadIdx.x, b = blockIdx.x;
    int lane = t & 31, w = t >> 5;
    int i = b * 256 + t;
    int v = (i < N) ? g_deg[i] : 0;

    // warp inclusive scan
    int inc = v;
#pragma unroll
    for (int o = 1; o < 32; o <<= 1) {
        int u = __shfl_up_sync(0xffffffffu, inc, o);
        if (lane >= o) inc += u;
    }
    if (lane == 31) wsum[w] = inc;
    __syncthreads();
    if (w == 0) {
        int ws = (lane < 8) ? wsum[lane] : 0;
#pragma unroll
        for (int o = 1; o < 8; o <<= 1) {
            int u = __shfl_up_sync(0xffffffffu, ws, o);
            if (lane >= o) ws += u;
        }
        if (lane < 8) wsum[lane] = ws;   // inclusive warp sums
    }
    __syncthreads();
    int wbase = (w > 0) ? wsum[w - 1] : 0;
    int incl  = wbase + inc;             // block-inclusive
    int total = wsum[7];

    if (t == 0) {
        if (b == 0) {
            g_blockpre[0] = total;
            __threadfence();
            g_flag[0] = 2;
            s_base = 0;
        } else {
            g_blockagg[b] = total;
            __threadfence();
            g_flag[b] = 1;
            int base = 0;
            for (int j = b - 1; j >= 0; j--) {
                int f;
                while ((f = g_flag[j]) == 0) { }
                if (f == 2) { base += g_blockpre[j]; break; }
                base += g_blockagg[j];
            }
            g_blockpre[b] = base + total;
            __threadfence();
            g_flag[b] = 2;
            s_base = base;
        }
    }
    __syncthreads();

    if (i < N) {
        int p = s_base + incl - v;   // exclusive
        g_rowptr[i] = p;
        g_cursor[i] = p;
    }
}

// ---------------------------------------------------------------------------
// K3: scatter dst into CSR buckets (2 edges/thread); block 0 resets scan flags.
// ---------------------------------------------------------------------------
__global__ void k_scatter(const int* __restrict__ edge, int E) {
    if (blockIdx.x == 0) g_flag[threadIdx.x] = 0;
    int i0 = (blockIdx.x * blockDim.x + threadIdx.x) * 2;
#pragma unroll
    for (int u = 0; u < 2; u++) {
        int i = i0 + u;
        if (i < E) {
            int s = edge[i];
            int d = edge[E + i];
            int pos = atomicAdd(&g_cursor[s], 1);
            g_csrdst[pos] = d;
        }
    }
}

// ---------------------------------------------------------------------------
// K4: fused aggregate + softmax + ELU. One warp per node; 32 edges per outer
// iteration. Parallel phase computes exp + pre-multiplied half2 index per
// edge; inner loop shuffles (ex, off) and gathers half2 payload.
// Also resets g_deg for the next call.
// No max-shift: scores bounded, exp safe in fp32; softmax shift-invariant.
// ---------------------------------------------------------------------------
__global__ __launch_bounds__(256) void k_agg(float* __restrict__ out, int N, int E) {
    int gwarp = (blockIdx.x * blockDim.x + threadIdx.x) >> 5;
    if (gwarp >= N) return;
    int lane = threadIdx.x & 31;

    if (lane == 0) g_deg[gwarp] = 0;   // reset for next call

    int start = g_rowptr[gwarp];
    int end   = (gwarp + 1 < N) ? g_rowptr[gwarp + 1] : E;
    float hs_n = g_hs[gwarp];

    const __half2* hlane = g_hh2 + lane;   // lane's column within any row
    float a0 = 0.0f, a1 = 0.0f, spart = 0.0f;

    for (int base = start; base < end; base += 32) {
        int i = base + lane;
        bool act = (i < end);
        int dst = act ? g_csrdst[i] : 0;          // coalesced
        float hdv = act ? g_hd[dst] : 0.0f;       // parallel gather
        float sc = hs_n + hdv;
        sc = sc > 0.0f ? sc : NEG_SLOPE * sc;
        float ex = act ? __expf(sc) : 0.0f;
        spart += ex;
        int off = dst * 32;                        // pre-multiplied half2 index

        int cnt = min(32, end - base);
#pragma unroll 4
        for (int j = 0; j < cnt; j++) {
            float exj = __shfl_sync(0xffffffffu, ex, j);
            int offj  = __shfl_sync(0xffffffffu, off, j);
            float2 v = __half22float2(hlane[offj]);
            a0 = fmaf(exj, v.x, a0);
            a1 = fmaf(exj, v.y, a1);
        }
    }

#pragma unroll
    for (int o = 16; o > 0; o >>= 1)
        spart += __shfl_xor_sync(0xffffffffu, spart, o);

    float2 r;
    if (spart > 0.0f) {
        float inv = 1.0f / spart;
        r.x = a0 * inv;
        r.y = a1 * inv;
    } else {
        r.x = 0.0f; r.y = 0.0f;
    }
    r.x = r.x > 0.0f ? r.x : expm1f(r.x);
    r.y = r.y > 0.0f ? r.y : expm1f(r.y);
    ((float2*)out)[(size_t)gwarp * 32 + lane] = r;
}

// ---------------------------------------------------------------------------
extern "C" void kernel_launch(void* const* d_in, const int* in_sizes, int n_in,
                              void* d_out, int out_size) {
    const float* inp  = (const float*)d_in[0];
    const int*   edge = (const int*)d_in[1];
    const float* Wg   = (const float*)d_in[2];
    const float* ag   = (const float*)d_in[3];
    float*       out  = (float*)d_out;

    int N = in_sizes[0] / IN_DIM;
    int E = in_sizes[1] / 2;
    int nchunks = (N + 255) / 256;   // <= 256 required (N <= 65536)

    k_gemm   <<<(N + 127) / 128, 256>>>(inp, Wg, ag, edge, N, E);  // + histogram
    k_scan   <<<nchunks, 256>>>(N);                                 // single-pass
    k_scatter<<<(E / 2 + 255) / 256, 256>>>(edge, E);               // + flag reset
    k_agg    <<<(N + 7) / 8, 256>>>(out, N, E);                     // + deg reset
}